// round 1
// baseline (speedup 1.0000x reference)
#include <cuda_runtime.h>
#include <cuda_bf16.h>

#define N_NODES 50000
#define N_EDGES 800000
#define CH      128
#define NGRAPH  64
#define SCAN_B  512
#define NBLK    ((N_NODES + SCAN_B - 1) / SCAN_B)   // 98

// ---------------- scratch (__device__ globals; no allocation) ----------------
__device__ int    d_deg[N_NODES];
__device__ int    d_off[N_NODES + 1];
__device__ int    d_cur[N_NODES];
__device__ int    d_csr[N_EDGES];
__device__ int    d_tmp[N_NODES];
__device__ int    d_bsum[NBLK];
__device__ int    d_bpref[NBLK];
__device__ float  d_dinv[N_NODES];
__device__ int    d_gcount[NGRAPH];
__device__ int    d_gstart[NGRAPH + 1];
__device__ float4 d_g4[N_NODES * (CH / 4)];   // g = dinv * (h @ W)
__device__ float4 d_h4[N_NODES * (CH / 4)];   // layer activations
__device__ float  d_pool[NGRAPH * CH];

// ---------------- setup kernels ----------------
__global__ void k_zero() {
    int i = blockIdx.x * blockDim.x + threadIdx.x;
    if (i < N_NODES) d_deg[i] = 0;
    if (i < NGRAPH)  d_gcount[i] = 0;
}

__global__ void k_hist(const int* __restrict__ dst, const int* __restrict__ batch) {
    int i = blockIdx.x * blockDim.x + threadIdx.x;
    if (i < N_EDGES) atomicAdd(&d_deg[dst[i]], 1);
    if (i < N_NODES) atomicAdd(&d_gcount[batch[i]], 1);
}

__global__ void k_scanA() {
    __shared__ int s[SCAN_B];
    int t = threadIdx.x;
    int i = blockIdx.x * SCAN_B + t;
    int x = (i < N_NODES) ? d_deg[i] : 0;
    s[t] = x;
    __syncthreads();
    for (int o = 1; o < SCAN_B; o <<= 1) {
        int v = (t >= o) ? s[t - o] : 0;
        __syncthreads();
        s[t] += v;
        __syncthreads();
    }
    if (i < N_NODES) d_tmp[i] = s[t];
    if (t == SCAN_B - 1) d_bsum[blockIdx.x] = s[t];
}

__global__ void k_scanB() {
    if (threadIdx.x == 0) {
        int a = 0;
        for (int b = 0; b < NBLK; b++) { d_bpref[b] = a; a += d_bsum[b]; }
        int c = 0;
        for (int g = 0; g < NGRAPH; g++) { d_gstart[g] = c; c += d_gcount[g]; }
        d_gstart[NGRAPH] = c;
    }
}

__global__ void k_scanC() {
    int i = blockIdx.x * blockDim.x + threadIdx.x;
    if (i >= N_NODES) return;
    int incl = d_tmp[i] + d_bpref[i / SCAN_B];
    int deg  = d_deg[i];
    d_off[i + 1] = incl;
    d_cur[i]     = incl - deg;
    d_dinv[i]    = rsqrtf((float)deg + 1.0f);
    if (i == 0) d_off[0] = 0;
}

__global__ void k_scatter(const int* __restrict__ src, const int* __restrict__ dst) {
    int e = blockIdx.x * blockDim.x + threadIdx.x;
    if (e >= N_EDGES) return;
    int p = atomicAdd(&d_cur[dst[e]], 1);
    d_csr[p] = src[e];
}

// ---------------- GEMM: g = dinv ⊙ (A @ W), A = [N,128], W = [128,128] -------
// block: 256 threads, tile 64x128, micro-tile 4x8
__global__ __launch_bounds__(256) void k_gemm(const float* __restrict__ A,
                                              const float* __restrict__ W) {
    __shared__ float As[16][64];
    __shared__ float Bs[16][128];
    const float* Aptr = A ? A : (const float*)d_h4;

    int tid = threadIdx.x;
    int tx = tid & 15;   // col group: cols tx*8 .. +7
    int ty = tid >> 4;   // row group: rows ty*4 .. +3
    int m0 = blockIdx.x * 64;

    float acc[4][8];
#pragma unroll
    for (int i = 0; i < 4; i++)
#pragma unroll
        for (int j = 0; j < 8; j++) acc[i][j] = 0.0f;

    int arow = tid >> 2;        // 0..63
    int ak   = (tid & 3) * 4;   // 0,4,8,12

    for (int kc = 0; kc < CH; kc += 16) {
        float4 av = make_float4(0.f, 0.f, 0.f, 0.f);
        if (m0 + arow < N_NODES)
            av = *(const float4*)&Aptr[(size_t)(m0 + arow) * CH + kc + ak];
        As[ak + 0][arow] = av.x;
        As[ak + 1][arow] = av.y;
        As[ak + 2][arow] = av.z;
        As[ak + 3][arow] = av.w;
#pragma unroll
        for (int i = 0; i < 2; i++) {
            int idx = tid + 256 * i;        // 0..511 float4 slots
            int kb  = idx >> 5;             // 0..15
            int c4  = idx & 31;             // 0..31
            *(float4*)&Bs[kb][c4 * 4] = *(const float4*)&W[(kc + kb) * CH + c4 * 4];
        }
        __syncthreads();
#pragma unroll
        for (int k = 0; k < 16; k++) {
            float a[4], b[8];
#pragma unroll
            for (int i = 0; i < 4; i++) a[i] = As[k][ty * 4 + i];
#pragma unroll
            for (int j = 0; j < 8; j++) b[j] = Bs[k][tx * 8 + j];
#pragma unroll
            for (int i = 0; i < 4; i++)
#pragma unroll
                for (int j = 0; j < 8; j++) acc[i][j] += a[i] * b[j];
        }
        __syncthreads();
    }

#pragma unroll
    for (int i = 0; i < 4; i++) {
        int row = m0 + ty * 4 + i;
        if (row < N_NODES) {
            float s = d_dinv[row];
            float* gout = (float*)d_g4;
            float4 v0 = make_float4(s * acc[i][0], s * acc[i][1], s * acc[i][2], s * acc[i][3]);
            float4 v1 = make_float4(s * acc[i][4], s * acc[i][5], s * acc[i][6], s * acc[i][7]);
            *(float4*)&gout[(size_t)row * CH + tx * 8]     = v0;
            *(float4*)&gout[(size_t)row * CH + tx * 8 + 4] = v1;
        }
    }
}

// ---------------- aggregation: h = relu(dinv_i * (g_i + Σ g_src) + b) --------
__global__ __launch_bounds__(256) void k_agg(const float* __restrict__ bias) {
    int gw = (blockIdx.x * blockDim.x + threadIdx.x) >> 5;
    if (gw >= N_NODES) return;
    int lane = threadIdx.x & 31;

    int beg = d_off[gw];
    int end = d_off[gw + 1];

    float4 acc = d_g4[gw * 32 + lane];   // self term
    int j = beg;
    for (; j + 4 <= end; j += 4) {
        int s0 = d_csr[j + 0];
        int s1 = d_csr[j + 1];
        int s2 = d_csr[j + 2];
        int s3 = d_csr[j + 3];
        float4 a = d_g4[s0 * 32 + lane];
        float4 b = d_g4[s1 * 32 + lane];
        float4 c = d_g4[s2 * 32 + lane];
        float4 d = d_g4[s3 * 32 + lane];
        acc.x += (a.x + b.x) + (c.x + d.x);
        acc.y += (a.y + b.y) + (c.y + d.y);
        acc.z += (a.z + b.z) + (c.z + d.z);
        acc.w += (a.w + b.w) + (c.w + d.w);
    }
    for (; j < end; j++) {
        float4 a = d_g4[d_csr[j] * 32 + lane];
        acc.x += a.x; acc.y += a.y; acc.z += a.z; acc.w += a.w;
    }

    float  s  = d_dinv[gw];
    float4 b4 = ((const float4*)bias)[lane];
    float4 r;
    r.x = fmaxf(fmaf(s, acc.x, b4.x), 0.0f);
    r.y = fmaxf(fmaf(s, acc.y, b4.y), 0.0f);
    r.z = fmaxf(fmaf(s, acc.z, b4.z), 0.0f);
    r.w = fmaxf(fmaf(s, acc.w, b4.w), 0.0f);
    d_h4[gw * 32 + lane] = r;
}

// ---------------- mean pool (batch is sorted → contiguous ranges) ------------
__global__ void k_pool() {
    int g = blockIdx.x;
    int c = threadIdx.x;  // 0..127
    int b = d_gstart[g], e = d_gstart[g + 1];
    const float* h = (const float*)d_h4;
    float s = 0.0f;
    for (int i = b; i < e; i++) s += h[(size_t)i * CH + c];
    float cnt = (float)(e - b);
    d_pool[g * CH + c] = s / fmaxf(cnt, 1.0f);
}

// ---------------- head: out = pooled @ Wc + bc -------------------------------
__global__ void k_final(const float* __restrict__ Wc, const float* __restrict__ bc,
                        float* __restrict__ out) {
    int t = threadIdx.x;
    if (t >= NGRAPH * 2) return;
    int g = t >> 1, o = t & 1;
    float s = 0.0f;
#pragma unroll 16
    for (int k = 0; k < CH; k++) s += d_pool[g * CH + k] * Wc[k * 2 + o];
    out[t] = s + bc[o];
}

// ---------------- launch -----------------------------------------------------
extern "C" void kernel_launch(void* const* d_in, const int* in_sizes, int n_in,
                              void* d_out, int out_size) {
    const float* x     = (const float*)d_in[0];
    const int*   ei    = (const int*)d_in[1];     // [2, E]: src then dst
    const int*   batch = (const int*)d_in[2];
    const float* W1 = (const float*)d_in[3];
    const float* b1 = (const float*)d_in[4];
    const float* W2 = (const float*)d_in[5];
    const float* b2 = (const float*)d_in[6];
    const float* W3 = (const float*)d_in[7];
    const float* b3 = (const float*)d_in[8];
    const float* Wc = (const float*)d_in[9];
    const float* bc = (const float*)d_in[10];
    float* out = (float*)d_out;

    const int* src = ei;
    const int* dst = ei + N_EDGES;

    int gN = (N_NODES + 255) / 256;
    int gE = (N_EDGES + 255) / 256;
    int gGemm = (N_NODES + 63) / 64;
    int gAgg  = (N_NODES * 32 + 255) / 256;

    k_zero<<<gN, 256>>>();
    k_hist<<<gE, 256>>>(dst, batch);
    k_scanA<<<NBLK, SCAN_B>>>();
    k_scanB<<<1, 32>>>();
    k_scanC<<<gN, 256>>>();
    k_scatter<<<gE, 256>>>(src, dst);

    // layer 1 (input x)
    k_gemm<<<gGemm, 256>>>(x, W1);
    k_agg<<<gAgg, 256>>>(b1);
    // layer 2
    k_gemm<<<gGemm, 256>>>(nullptr, W2);
    k_agg<<<gAgg, 256>>>(b2);
    // layer 3
    k_gemm<<<gGemm, 256>>>(nullptr, W3);
    k_agg<<<gAgg, 256>>>(b3);

    k_pool<<<NGRAPH, CH>>>();
    k_final<<<1, 128>>>(Wc, bc, out);
}

// round 3
// speedup vs baseline: 1.1258x; 1.1258x over previous
#include <cuda_runtime.h>
#include <cuda_bf16.h>

#define N_NODES 50000
#define N_EDGES 800000
#define CH      128
#define NGRAPH  64
#define SCAN_B  512
#define NBLK    ((N_NODES + SCAN_B - 1) / SCAN_B)   // 98

// ---------------- scratch (__device__ globals; no allocation) ----------------
__device__ int    d_deg[N_NODES];
__device__ int    d_off[N_NODES + 1];
__device__ int    d_cur[N_NODES];
__device__ int    d_csr[N_EDGES];
__device__ int    d_tmp[N_NODES];
__device__ int    d_bsum[NBLK];
__device__ int    d_bpref[NBLK];
__device__ float  d_dinv[N_NODES];
__device__ int    d_gcount[NGRAPH];
__device__ int    d_gstart[NGRAPH + 1];
__device__ float4 d_g4[N_NODES * (CH / 4)];   // g = dinv * (h @ W)
__device__ float4 d_h4[N_NODES * (CH / 4)];   // layer activations
__device__ float  d_pool[NGRAPH * CH];

// ---------------- setup kernels ----------------
__global__ void k_zero() {
    int i = blockIdx.x * blockDim.x + threadIdx.x;
    if (i < N_NODES) d_deg[i] = 0;
    if (i < NGRAPH)  d_gcount[i] = 0;
}

__global__ void k_hist(const int* __restrict__ dst, const int* __restrict__ batch) {
    int i = blockIdx.x * blockDim.x + threadIdx.x;
    if (i < N_EDGES) atomicAdd(&d_deg[dst[i]], 1);
    if (i < N_NODES) atomicAdd(&d_gcount[batch[i]], 1);
}

__global__ void k_scanA() {
    __shared__ int s[SCAN_B];
    int t = threadIdx.x;
    int i = blockIdx.x * SCAN_B + t;
    int x = (i < N_NODES) ? d_deg[i] : 0;
    s[t] = x;
    __syncthreads();
    for (int o = 1; o < SCAN_B; o <<= 1) {
        int v = (t >= o) ? s[t - o] : 0;
        __syncthreads();
        s[t] += v;
        __syncthreads();
    }
    if (i < N_NODES) d_tmp[i] = s[t];
    if (t == SCAN_B - 1) d_bsum[blockIdx.x] = s[t];
}

// parallel scan over block sums (98) and graph counts (64) in one 128-thread block
__global__ void k_scanB() {
    __shared__ int s[128];
    int t = threadIdx.x;

    int v = (t < NBLK) ? d_bsum[t] : 0;
    s[t] = v;
    __syncthreads();
#pragma unroll
    for (int o = 1; o < 128; o <<= 1) {
        int u = (t >= o) ? s[t - o] : 0;
        __syncthreads();
        s[t] += u;
        __syncthreads();
    }
    if (t < NBLK) d_bpref[t] = s[t] - v;   // exclusive prefix
    __syncthreads();

    int c = (t < NGRAPH) ? d_gcount[t] : 0;
    s[t] = c;
    __syncthreads();
#pragma unroll
    for (int o = 1; o < 128; o <<= 1) {
        int u = (t >= o) ? s[t - o] : 0;
        __syncthreads();
        s[t] += u;
        __syncthreads();
    }
    if (t < NGRAPH) d_gstart[t] = s[t] - c;
    if (t == NGRAPH - 1) d_gstart[NGRAPH] = s[t];
}

__global__ void k_scanC() {
    int i = blockIdx.x * blockDim.x + threadIdx.x;
    if (i >= N_NODES) return;
    int incl = d_tmp[i] + d_bpref[i / SCAN_B];
    int deg  = d_deg[i];
    d_off[i + 1] = incl;
    d_cur[i]     = incl - deg;
    d_dinv[i]    = rsqrtf((float)deg + 1.0f);
    if (i == 0) d_off[0] = 0;
}

__global__ void k_scatter(const int* __restrict__ src, const int* __restrict__ dst) {
    int e = blockIdx.x * blockDim.x + threadIdx.x;
    if (e >= N_EDGES) return;
    int p = atomicAdd(&d_cur[dst[e]], 1);
    d_csr[p] = src[e];
}

// ---------------- GEMM: g = dinv ⊙ (A @ W), A = [N,128], W = [128,128] -------
// block: 256 threads, tile 128x128, micro-tile 8x8, float4 smem traffic
__global__ __launch_bounds__(256) void k_gemm(const float* __restrict__ A,
                                              const float* __restrict__ W) {
    __shared__ float As[16][128];   // [k][row]
    __shared__ float Bs[16][128];   // [k][col]
    const float* Aptr = A ? A : (const float*)d_h4;

    int tid = threadIdx.x;
    int tx = tid & 15;   // col group: cols tx*8 .. +7
    int ty = tid >> 4;   // row group: rows ty*8 .. +7
    int m0 = blockIdx.x * 128;

    float acc[8][8];
#pragma unroll
    for (int i = 0; i < 8; i++)
#pragma unroll
        for (int j = 0; j < 8; j++) acc[i][j] = 0.0f;

    for (int kc = 0; kc < CH; kc += 16) {
#pragma unroll
        for (int i = 0; i < 2; i++) {
            int idx = tid + 256 * i;        // 0..511 float4 slots
            // A tile: 128 rows x 16 k
            int row = idx >> 2;
            int q   = (idx & 3) * 4;
            float4 av = make_float4(0.f, 0.f, 0.f, 0.f);
            if (m0 + row < N_NODES)
                av = *(const float4*)&Aptr[(size_t)(m0 + row) * CH + kc + q];
            As[q + 0][row] = av.x;
            As[q + 1][row] = av.y;
            As[q + 2][row] = av.z;
            As[q + 3][row] = av.w;
            // B tile: 16 k x 128 cols
            int kb = idx >> 5;
            int c4 = idx & 31;
            *(float4*)&Bs[kb][c4 * 4] = *(const float4*)&W[(kc + kb) * CH + c4 * 4];
        }
        __syncthreads();
#pragma unroll
        for (int k = 0; k < 16; k++) {
            float a[8], b[8];
            *(float4*)&a[0] = *(const float4*)&As[k][ty * 8];
            *(float4*)&a[4] = *(const float4*)&As[k][ty * 8 + 4];
            *(float4*)&b[0] = *(const float4*)&Bs[k][tx * 8];
            *(float4*)&b[4] = *(const float4*)&Bs[k][tx * 8 + 4];
#pragma unroll
            for (int i = 0; i < 8; i++)
#pragma unroll
                for (int j = 0; j < 8; j++) acc[i][j] = fmaf(a[i], b[j], acc[i][j]);
        }
        __syncthreads();
    }

    float* gout = (float*)d_g4;
#pragma unroll
    for (int i = 0; i < 8; i++) {
        int row = m0 + ty * 8 + i;
        if (row < N_NODES) {
            float s = d_dinv[row];
            float4 v0 = make_float4(s * acc[i][0], s * acc[i][1], s * acc[i][2], s * acc[i][3]);
            float4 v1 = make_float4(s * acc[i][4], s * acc[i][5], s * acc[i][6], s * acc[i][7]);
            *(float4*)&gout[(size_t)row * CH + tx * 8]     = v0;
            *(float4*)&gout[(size_t)row * CH + tx * 8 + 4] = v1;
        }
    }
}

// ---------------- aggregation: h = relu(dinv_i * (g_i + Σ g_src) + b) --------
__global__ __launch_bounds__(256) void k_agg(const float* __restrict__ bias) {
    int gw = (blockIdx.x * blockDim.x + threadIdx.x) >> 5;
    if (gw >= N_NODES) return;
    int lane = threadIdx.x & 31;

    int beg = d_off[gw];
    int end = d_off[gw + 1];

    float4 acc = d_g4[gw * 32 + lane];   // self term
    int j = beg;
    for (; j + 8 <= end; j += 8) {
        int s0 = d_csr[j + 0];
        int s1 = d_csr[j + 1];
        int s2 = d_csr[j + 2];
        int s3 = d_csr[j + 3];
        int s4 = d_csr[j + 4];
        int s5 = d_csr[j + 5];
        int s6 = d_csr[j + 6];
        int s7 = d_csr[j + 7];
        float4 a0 = d_g4[s0 * 32 + lane];
        float4 a1 = d_g4[s1 * 32 + lane];
        float4 a2 = d_g4[s2 * 32 + lane];
        float4 a3 = d_g4[s3 * 32 + lane];
        float4 a4 = d_g4[s4 * 32 + lane];
        float4 a5 = d_g4[s5 * 32 + lane];
        float4 a6 = d_g4[s6 * 32 + lane];
        float4 a7 = d_g4[s7 * 32 + lane];
        acc.x += ((a0.x + a1.x) + (a2.x + a3.x)) + ((a4.x + a5.x) + (a6.x + a7.x));
        acc.y += ((a0.y + a1.y) + (a2.y + a3.y)) + ((a4.y + a5.y) + (a6.y + a7.y));
        acc.z += ((a0.z + a1.z) + (a2.z + a3.z)) + ((a4.z + a5.z) + (a6.z + a7.z));
        acc.w += ((a0.w + a1.w) + (a2.w + a3.w)) + ((a4.w + a5.w) + (a6.w + a7.w));
    }
    for (; j < end; j++) {
        float4 a = d_g4[d_csr[j] * 32 + lane];
        acc.x += a.x; acc.y += a.y; acc.z += a.z; acc.w += a.w;
    }

    float  s  = d_dinv[gw];
    float4 b4 = ((const float4*)bias)[lane];
    float4 r;
    r.x = fmaxf(fmaf(s, acc.x, b4.x), 0.0f);
    r.y = fmaxf(fmaf(s, acc.y, b4.y), 0.0f);
    r.z = fmaxf(fmaf(s, acc.z, b4.z), 0.0f);
    r.w = fmaxf(fmaf(s, acc.w, b4.w), 0.0f);
    d_h4[gw * 32 + lane] = r;
}

// ---------------- mean pool (batch is sorted → contiguous ranges) ------------
// MUST be launched with 512 threads (4 segments x 128 channels)
__global__ __launch_bounds__(512) void k_pool() {
    __shared__ float red[4][CH];
    int g   = blockIdx.x;
    int c   = threadIdx.x & 127;
    int seg = threadIdx.x >> 7;   // 0..3
    int b = d_gstart[g], e = d_gstart[g + 1];
    const float* h = (const float*)d_h4;
    float s = 0.0f;
    for (int i = b + seg; i < e; i += 4) s += h[(size_t)i * CH + c];
    red[seg][c] = s;
    __syncthreads();
    if (seg == 0) {
        float tot = (red[0][c] + red[1][c]) + (red[2][c] + red[3][c]);
        float cnt = (float)(e - b);
        d_pool[g * CH + c] = tot / fmaxf(cnt, 1.0f);
    }
}

// ---------------- head: out = pooled @ Wc + bc -------------------------------
__global__ void k_final(const float* __restrict__ Wc, const float* __restrict__ bc,
                        float* __restrict__ out) {
    int t = threadIdx.x;
    if (t >= NGRAPH * 2) return;
    int g = t >> 1, o = t & 1;
    float s = 0.0f;
#pragma unroll 16
    for (int k = 0; k < CH; k++) s += d_pool[g * CH + k] * Wc[k * 2 + o];
    out[t] = s + bc[o];
}

// ---------------- launch -----------------------------------------------------
extern "C" void kernel_launch(void* const* d_in, const int* in_sizes, int n_in,
                              void* d_out, int out_size) {
    const float* x     = (const float*)d_in[0];
    const int*   ei    = (const int*)d_in[1];     // [2, E]: src then dst
    const int*   batch = (const int*)d_in[2];
    const float* W1 = (const float*)d_in[3];
    const float* b1 = (const float*)d_in[4];
    const float* W2 = (const float*)d_in[5];
    const float* b2 = (const float*)d_in[6];
    const float* W3 = (const float*)d_in[7];
    const float* b3 = (const float*)d_in[8];
    const float* Wc = (const float*)d_in[9];
    const float* bc = (const float*)d_in[10];
    float* out = (float*)d_out;

    const int* src = ei;
    const int* dst = ei + N_EDGES;

    int gN = (N_NODES + 255) / 256;
    int gE = (N_EDGES + 255) / 256;
    int gGemm = (N_NODES + 127) / 128;
    int gAgg  = (N_NODES * 32 + 255) / 256;

    k_zero<<<gN, 256>>>();
    k_hist<<<gE, 256>>>(dst, batch);
    k_scanA<<<NBLK, SCAN_B>>>();
    k_scanB<<<1, 128>>>();
    k_scanC<<<gN, 256>>>();
    k_scatter<<<gE, 256>>>(src, dst);

    // layer 1 (input x)
    k_gemm<<<gGemm, 256>>>(x, W1);
    k_agg<<<gAgg, 256>>>(b1);
    // layer 2
    k_gemm<<<gGemm, 256>>>(nullptr, W2);
    k_agg<<<gAgg, 256>>>(b2);
    // layer 3
    k_gemm<<<gGemm, 256>>>(nullptr, W3);
    k_agg<<<gAgg, 256>>>(b3);

    k_pool<<<NGRAPH, 512>>>();
    k_final<<<1, 128>>>(Wc, bc, out);
}

// round 5
// speedup vs baseline: 1.3704x; 1.2173x over previous
#include <cuda_runtime.h>
#include <cuda_bf16.h>

#define N_NODES 50000
#define N_EDGES 800000
#define CH      128
#define NGRAPH  64
#define SCAN_B  512
#define NBLK    ((N_NODES + SCAN_B - 1) / SCAN_B)   // 98

// ---------------- scratch (__device__ globals; no allocation) ----------------
__device__ int    d_deg[N_NODES];
__device__ int    d_off[N_NODES + 1];
__device__ int    d_cur[N_NODES];
__device__ int    d_csr[N_EDGES];
__device__ int    d_tmp[N_NODES];
__device__ int    d_bsum[NBLK];
__device__ int    d_bpref[NBLK];
__device__ float  d_dinv[N_NODES];
__device__ int    d_gcount[NGRAPH];
__device__ int    d_gstart[NGRAPH + 1];
__device__ uint2  d_g[N_NODES * (CH / 4)];    // g = dinv * (h @ W), bf16 (4 ch per uint2)
__device__ float4 d_h4[N_NODES * (CH / 4)];   // layer activations, fp32
__device__ float  d_pool[NGRAPH * CH];

// ---------------- setup kernels ----------------
__global__ void k_zero() {
    int i = blockIdx.x * blockDim.x + threadIdx.x;
    if (i < N_NODES) d_deg[i] = 0;
    if (i < NGRAPH)  d_gcount[i] = 0;
}

__global__ void k_hist(const int* __restrict__ dst, const int* __restrict__ batch) {
    int i = blockIdx.x * blockDim.x + threadIdx.x;
    if (i < N_EDGES) atomicAdd(&d_deg[dst[i]], 1);
    if (i < N_NODES) atomicAdd(&d_gcount[batch[i]], 1);
}

__global__ void k_scanA() {
    __shared__ int s[SCAN_B];
    int t = threadIdx.x;
    int i = blockIdx.x * SCAN_B + t;
    int x = (i < N_NODES) ? d_deg[i] : 0;
    s[t] = x;
    __syncthreads();
    for (int o = 1; o < SCAN_B; o <<= 1) {
        int v = (t >= o) ? s[t - o] : 0;
        __syncthreads();
        s[t] += v;
        __syncthreads();
    }
    if (i < N_NODES) d_tmp[i] = s[t];
    if (t == SCAN_B - 1) d_bsum[blockIdx.x] = s[t];
}

__global__ void k_scanB() {
    __shared__ int s[128];
    int t = threadIdx.x;

    int v = (t < NBLK) ? d_bsum[t] : 0;
    s[t] = v;
    __syncthreads();
#pragma unroll
    for (int o = 1; o < 128; o <<= 1) {
        int u = (t >= o) ? s[t - o] : 0;
        __syncthreads();
        s[t] += u;
        __syncthreads();
    }
    if (t < NBLK) d_bpref[t] = s[t] - v;
    __syncthreads();

    int c = (t < NGRAPH) ? d_gcount[t] : 0;
    s[t] = c;
    __syncthreads();
#pragma unroll
    for (int o = 1; o < 128; o <<= 1) {
        int u = (t >= o) ? s[t - o] : 0;
        __syncthreads();
        s[t] += u;
        __syncthreads();
    }
    if (t < NGRAPH) d_gstart[t] = s[t] - c;
    if (t == NGRAPH - 1) d_gstart[NGRAPH] = s[t];
}

__global__ void k_scanC() {
    int i = blockIdx.x * blockDim.x + threadIdx.x;
    if (i >= N_NODES) return;
    int incl = d_tmp[i] + d_bpref[i / SCAN_B];
    int deg  = d_deg[i];
    d_off[i + 1] = incl;
    d_cur[i]     = incl - deg;
    d_dinv[i]    = rsqrtf((float)deg + 1.0f);
    if (i == 0) d_off[0] = 0;
}

__global__ void k_scatter(const int* __restrict__ src, const int* __restrict__ dst) {
    int e = blockIdx.x * blockDim.x + threadIdx.x;
    if (e >= N_EDGES) return;
    int p = atomicAdd(&d_cur[dst[e]], 1);
    d_csr[p] = src[e];
}

// ---------------- GEMM: g = bf16(dinv ⊙ (A @ W)), A=[N,128] fp32, W=[128,128]
// block: 256 threads, tile 128x128, micro-tile 8x8, float4 smem traffic (R3-proven)
__global__ __launch_bounds__(256) void k_gemm(const float* __restrict__ A,
                                              const float* __restrict__ W) {
    __shared__ float As[16][128];   // [k][row]
    __shared__ float Bs[16][128];   // [k][col]
    const float* Aptr = A ? A : (const float*)d_h4;

    int tid = threadIdx.x;
    int tx = tid & 15;   // col group: cols tx*8 .. +7
    int ty = tid >> 4;   // row group: rows ty*8 .. +7
    int m0 = blockIdx.x * 128;

    float acc[8][8];
#pragma unroll
    for (int i = 0; i < 8; i++)
#pragma unroll
        for (int j = 0; j < 8; j++) acc[i][j] = 0.0f;

    for (int kc = 0; kc < CH; kc += 16) {
#pragma unroll
        for (int i = 0; i < 2; i++) {
            int idx = tid + 256 * i;        // 0..511 float4 slots
            int row = idx >> 2;
            int q   = (idx & 3) * 4;
            float4 av = make_float4(0.f, 0.f, 0.f, 0.f);
            if (m0 + row < N_NODES)
                av = *(const float4*)&Aptr[(size_t)(m0 + row) * CH + kc + q];
            As[q + 0][row] = av.x;
            As[q + 1][row] = av.y;
            As[q + 2][row] = av.z;
            As[q + 3][row] = av.w;
            int kb = idx >> 5;
            int c4 = idx & 31;
            *(float4*)&Bs[kb][c4 * 4] = *(const float4*)&W[(kc + kb) * CH + c4 * 4];
        }
        __syncthreads();
#pragma unroll
        for (int k = 0; k < 16; k++) {
            float a[8], b[8];
            *(float4*)&a[0] = *(const float4*)&As[k][ty * 8];
            *(float4*)&a[4] = *(const float4*)&As[k][ty * 8 + 4];
            *(float4*)&b[0] = *(const float4*)&Bs[k][tx * 8];
            *(float4*)&b[4] = *(const float4*)&Bs[k][tx * 8 + 4];
#pragma unroll
            for (int i = 0; i < 8; i++)
#pragma unroll
                for (int j = 0; j < 8; j++) acc[i][j] = fmaf(a[i], b[j], acc[i][j]);
        }
        __syncthreads();
    }

    // epilogue: scale by dinv, convert to bf16, write g (8 ch = 2 uint2 per thread-row)
#pragma unroll
    for (int i = 0; i < 8; i++) {
        int row = m0 + ty * 8 + i;
        if (row < N_NODES) {
            float s = d_dinv[row];
            __nv_bfloat162 p0 = __floats2bfloat162_rn(s * acc[i][0], s * acc[i][1]);
            __nv_bfloat162 p1 = __floats2bfloat162_rn(s * acc[i][2], s * acc[i][3]);
            __nv_bfloat162 p2 = __floats2bfloat162_rn(s * acc[i][4], s * acc[i][5]);
            __nv_bfloat162 p3 = __floats2bfloat162_rn(s * acc[i][6], s * acc[i][7]);
            uint2 u0, u1;
            *reinterpret_cast<__nv_bfloat162*>(&u0.x) = p0;
            *reinterpret_cast<__nv_bfloat162*>(&u0.y) = p1;
            *reinterpret_cast<__nv_bfloat162*>(&u1.x) = p2;
            *reinterpret_cast<__nv_bfloat162*>(&u1.y) = p3;
            d_g[(size_t)row * 32 + tx * 2 + 0] = u0;
            d_g[(size_t)row * 32 + tx * 2 + 1] = u1;
        }
    }
}

// ---------------- aggregation: h = relu(dinv_i * (g_i + Σ g_src) + b) --------
__device__ __forceinline__ float4 ld_g(int row, int lane) {
    uint2 u = __ldg(&d_g[(size_t)row * 32 + lane]);
    float2 f0 = __bfloat1622float2(*reinterpret_cast<__nv_bfloat162*>(&u.x));
    float2 f1 = __bfloat1622float2(*reinterpret_cast<__nv_bfloat162*>(&u.y));
    return make_float4(f0.x, f0.y, f1.x, f1.y);
}

__global__ __launch_bounds__(256) void k_agg(const float* __restrict__ bias) {
    int gw = (blockIdx.x * blockDim.x + threadIdx.x) >> 5;
    if (gw >= N_NODES) return;
    int lane = threadIdx.x & 31;

    int beg = d_off[gw];
    int end = d_off[gw + 1];

    float4 acc = ld_g(gw, lane);   // self term
    int j = beg;
    for (; j + 8 <= end; j += 8) {
        int s0 = d_csr[j + 0];
        int s1 = d_csr[j + 1];
        int s2 = d_csr[j + 2];
        int s3 = d_csr[j + 3];
        int s4 = d_csr[j + 4];
        int s5 = d_csr[j + 5];
        int s6 = d_csr[j + 6];
        int s7 = d_csr[j + 7];
        float4 a0 = ld_g(s0, lane);
        float4 a1 = ld_g(s1, lane);
        float4 a2 = ld_g(s2, lane);
        float4 a3 = ld_g(s3, lane);
        float4 a4 = ld_g(s4, lane);
        float4 a5 = ld_g(s5, lane);
        float4 a6 = ld_g(s6, lane);
        float4 a7 = ld_g(s7, lane);
        acc.x += ((a0.x + a1.x) + (a2.x + a3.x)) + ((a4.x + a5.x) + (a6.x + a7.x));
        acc.y += ((a0.y + a1.y) + (a2.y + a3.y)) + ((a4.y + a5.y) + (a6.y + a7.y));
        acc.z += ((a0.z + a1.z) + (a2.z + a3.z)) + ((a4.z + a5.z) + (a6.z + a7.z));
        acc.w += ((a0.w + a1.w) + (a2.w + a3.w)) + ((a4.w + a5.w) + (a6.w + a7.w));
    }
    for (; j < end; j++) {
        float4 a = ld_g(d_csr[j], lane);
        acc.x += a.x; acc.y += a.y; acc.z += a.z; acc.w += a.w;
    }

    float  s  = d_dinv[gw];
    float4 b4 = ((const float4*)bias)[lane];
    float4 r;
    r.x = fmaxf(fmaf(s, acc.x, b4.x), 0.0f);
    r.y = fmaxf(fmaf(s, acc.y, b4.y), 0.0f);
    r.z = fmaxf(fmaf(s, acc.z, b4.z), 0.0f);
    r.w = fmaxf(fmaf(s, acc.w, b4.w), 0.0f);
    d_h4[gw * 32 + lane] = r;
}

// ---------------- mean pool (batch is sorted → contiguous ranges) ------------
// launch with 512 threads (4 segments x 128 channels)
__global__ __launch_bounds__(512) void k_pool() {
    __shared__ float red[4][CH];
    int g   = blockIdx.x;
    int c   = threadIdx.x & 127;
    int seg = threadIdx.x >> 7;
    int b = d_gstart[g], e = d_gstart[g + 1];
    const float* h = (const float*)d_h4;
    float s = 0.0f;
    for (int i = b + seg; i < e; i += 4) s += h[(size_t)i * CH + c];
    red[seg][c] = s;
    __syncthreads();
    if (seg == 0) {
        float tot = (red[0][c] + red[1][c]) + (red[2][c] + red[3][c]);
        float cnt = (float)(e - b);
        d_pool[g * CH + c] = tot / fmaxf(cnt, 1.0f);
    }
}

// ---------------- head: out = pooled @ Wc + bc -------------------------------
__global__ void k_final(const float* __restrict__ Wc, const float* __restrict__ bc,
                        float* __restrict__ out) {
    int t = threadIdx.x;
    if (t >= NGRAPH * 2) return;
    int g = t >> 1, o = t & 1;
    float s = 0.0f;
#pragma unroll 16
    for (int k = 0; k < CH; k++) s += d_pool[g * CH + k] * Wc[k * 2 + o];
    out[t] = s + bc[o];
}

// ---------------- launch -----------------------------------------------------
extern "C" void kernel_launch(void* const* d_in, const int* in_sizes, int n_in,
                              void* d_out, int out_size) {
    const float* x     = (const float*)d_in[0];
    const int*   ei    = (const int*)d_in[1];     // [2, E]: src then dst
    const int*   batch = (const int*)d_in[2];
    const float* W1 = (const float*)d_in[3];
    const float* b1 = (const float*)d_in[4];
    const float* W2 = (const float*)d_in[5];
    const float* b2 = (const float*)d_in[6];
    const float* W3 = (const float*)d_in[7];
    const float* b3 = (const float*)d_in[8];
    const float* Wc = (const float*)d_in[9];
    const float* bc = (const float*)d_in[10];
    float* out = (float*)d_out;

    const int* src = ei;
    const int* dst = ei + N_EDGES;

    int gN = (N_NODES + 255) / 256;
    int gE = (N_EDGES + 255) / 256;
    int gGemm = (N_NODES + 127) / 128;
    int gAgg  = (N_NODES * 32 + 255) / 256;

    k_zero<<<gN, 256>>>();
    k_hist<<<gE, 256>>>(dst, batch);
    k_scanA<<<NBLK, SCAN_B>>>();
    k_scanB<<<1, 128>>>();
    k_scanC<<<gN, 256>>>();
    k_scatter<<<gE, 256>>>(src, dst);

    // layer 1 (input x)
    k_gemm<<<gGemm, 256>>>(x, W1);
    k_agg<<<gAgg, 256>>>(b1);
    // layer 2
    k_gemm<<<gGemm, 256>>>(nullptr, W2);
    k_agg<<<gAgg, 256>>>(b2);
    // layer 3
    k_gemm<<<gGemm, 256>>>(nullptr, W3);
    k_agg<<<gAgg, 256>>>(b3);

    k_pool<<<NGRAPH, 512>>>();
    k_final<<<1, 128>>>(Wc, bc, out);
}

// round 6
// speedup vs baseline: 1.4235x; 1.0388x over previous
#include <cuda_runtime.h>
#include <cuda_bf16.h>

#define N_NODES 50000
#define N_EDGES 800000
#define CH      128
#define NGRAPH  64
#define SCAN_B  512
#define NBLK    ((N_NODES + SCAN_B - 1) / SCAN_B)   // 98

// ---------------- scratch (__device__ globals; no allocation) ----------------
__device__ int    d_deg[N_NODES];
__device__ int    d_off[N_NODES + 1];
__device__ int    d_cur[N_NODES];
__device__ int    d_csr[N_EDGES];
__device__ int    d_tmp[N_NODES];
__device__ int    d_bsum[NBLK];
__device__ int    d_bpref[NBLK];
__device__ float  d_dinv[N_NODES];
__device__ int    d_gcount[NGRAPH];
__device__ int    d_gstart[NGRAPH + 1];
__device__ uint2  d_g[N_NODES * (CH / 4)];    // g = dinv * (h @ W), bf16 (4 ch per uint2)
__device__ float4 d_h4[N_NODES * (CH / 4)];   // layer activations, fp32
__device__ float  d_pool[NGRAPH * CH];

// ---------------- setup kernels ----------------
__global__ void k_zero() {
    int i = blockIdx.x * blockDim.x + threadIdx.x;
    if (i < N_NODES) d_deg[i] = 0;
    if (i < NGRAPH)  d_gcount[i] = 0;
}

__global__ void k_hist(const int* __restrict__ dst, const int* __restrict__ batch) {
    int i = blockIdx.x * blockDim.x + threadIdx.x;
    if (i < N_EDGES) atomicAdd(&d_deg[dst[i]], 1);
    if (i < N_NODES) atomicAdd(&d_gcount[batch[i]], 1);
}

__global__ void k_scanA() {
    __shared__ int s[SCAN_B];
    int t = threadIdx.x;
    int i = blockIdx.x * SCAN_B + t;
    int x = (i < N_NODES) ? d_deg[i] : 0;
    s[t] = x;
    __syncthreads();
    for (int o = 1; o < SCAN_B; o <<= 1) {
        int v = (t >= o) ? s[t - o] : 0;
        __syncthreads();
        s[t] += v;
        __syncthreads();
    }
    if (i < N_NODES) d_tmp[i] = s[t];
    if (t == SCAN_B - 1) d_bsum[blockIdx.x] = s[t];
}

__global__ void k_scanB() {
    __shared__ int s[128];
    int t = threadIdx.x;

    int v = (t < NBLK) ? d_bsum[t] : 0;
    s[t] = v;
    __syncthreads();
#pragma unroll
    for (int o = 1; o < 128; o <<= 1) {
        int u = (t >= o) ? s[t - o] : 0;
        __syncthreads();
        s[t] += u;
        __syncthreads();
    }
    if (t < NBLK) d_bpref[t] = s[t] - v;
    __syncthreads();

    int c = (t < NGRAPH) ? d_gcount[t] : 0;
    s[t] = c;
    __syncthreads();
#pragma unroll
    for (int o = 1; o < 128; o <<= 1) {
        int u = (t >= o) ? s[t - o] : 0;
        __syncthreads();
        s[t] += u;
        __syncthreads();
    }
    if (t < NGRAPH) d_gstart[t] = s[t] - c;
    if (t == NGRAPH - 1) d_gstart[NGRAPH] = s[t];
}

__global__ void k_scanC() {
    int i = blockIdx.x * blockDim.x + threadIdx.x;
    if (i >= N_NODES) return;
    int incl = d_tmp[i] + d_bpref[i / SCAN_B];
    int deg  = d_deg[i];
    d_off[i + 1] = incl;
    d_cur[i]     = incl - deg;
    d_dinv[i]    = rsqrtf((float)deg + 1.0f);
    if (i == 0) d_off[0] = 0;
}

__global__ void k_scatter(const int* __restrict__ src, const int* __restrict__ dst) {
    int e = blockIdx.x * blockDim.x + threadIdx.x;
    if (e >= N_EDGES) return;
    int p = atomicAdd(&d_cur[dst[e]], 1);
    d_csr[p] = src[e];
}

// ---------------- tf32 helpers ----------------
__device__ __forceinline__ unsigned f2tf32(float f) {
    unsigned u;
    asm("cvt.rna.tf32.f32 %0, %1;" : "=r"(u) : "f"(f));
    return u;
}

__device__ __forceinline__ void mma_tf32(float c[4], unsigned a0, unsigned a1,
                                         unsigned a2, unsigned a3,
                                         unsigned b0, unsigned b1) {
    asm volatile(
        "mma.sync.aligned.m16n8k8.row.col.f32.tf32.tf32.f32 "
        "{%0,%1,%2,%3}, {%4,%5,%6,%7}, {%8,%9}, {%0,%1,%2,%3};"
        : "+f"(c[0]), "+f"(c[1]), "+f"(c[2]), "+f"(c[3])
        : "r"(a0), "r"(a1), "r"(a2), "r"(a3), "r"(b0), "r"(b1));
}

// ---------------- GEMM: g = bf16(dinv ⊙ (A @ W)) via tf32 mma ----------------
// A [N,128] fp32 (single tf32), W [128,128] fp32 split tf32 hi+lo.
// block 256 thr = 8 warps; block tile M=128 x N=128; warp: 16 rows x 128 cols.
// k-chunk 16 staged in smem; per chunk: 2 k8-steps x 16 n-tiles x 2(split) mma.
#define APAD 20
#define BPAD 132
__global__ __launch_bounds__(256) void k_gemm_tc(const float* __restrict__ A_,
                                                 const float* __restrict__ W) {
    __shared__ float As[128][APAD];   // [row][k] fp32 (16 used)
    __shared__ float Bh[16][BPAD];    // [k][n] tf32-hi as float
    __shared__ float Bl[16][BPAD];    // [k][n] tf32-lo as float

    const float* Aptr = A_ ? A_ : (const float*)d_h4;

    int tid  = threadIdx.x;
    int wid  = tid >> 5;
    int lane = tid & 31;
    int g    = lane >> 2;   // 0..7
    int q    = lane & 3;    // 0..3
    int m0   = blockIdx.x * 128;
    int wm   = wid * 16;    // warp row strip inside block tile

    float acc[16][4];
#pragma unroll
    for (int nt = 0; nt < 16; nt++)
#pragma unroll
        for (int j = 0; j < 4; j++) acc[nt][j] = 0.0f;

    for (int kc = 0; kc < CH; kc += 16) {
        // stage A: 128 rows x 16 k  (512 float4, 2 per thread)
#pragma unroll
        for (int i = 0; i < 2; i++) {
            int idx = tid + 256 * i;
            int row = idx >> 2;
            int q4  = (idx & 3) * 4;
            float4 av = make_float4(0.f, 0.f, 0.f, 0.f);
            if (m0 + row < N_NODES)
                av = *(const float4*)&Aptr[(size_t)(m0 + row) * CH + kc + q4];
            *(float4*)&As[row][q4] = av;
        }
        // stage W chunk split: 16 k x 128 n (512 float4, 2 per thread)
#pragma unroll
        for (int i = 0; i < 2; i++) {
            int idx = tid + 256 * i;
            int kb = idx >> 5;           // 0..15
            int n4 = (idx & 31) * 4;     // 0..124
            float4 wv = *(const float4*)&W[(kc + kb) * CH + n4];
            float wf[4] = {wv.x, wv.y, wv.z, wv.w};
#pragma unroll
            for (int j = 0; j < 4; j++) {
                float hi = __uint_as_float(f2tf32(wf[j]));
                float lo = __uint_as_float(f2tf32(wf[j] - hi));
                Bh[kb][n4 + j] = hi;
                Bl[kb][n4 + j] = lo;
            }
        }
        __syncthreads();

#pragma unroll
        for (int ks = 0; ks < 2; ks++) {
            int k8 = ks * 8;
            unsigned a0 = f2tf32(As[wm + g][k8 + q]);
            unsigned a1 = f2tf32(As[wm + g + 8][k8 + q]);
            unsigned a2 = f2tf32(As[wm + g][k8 + q + 4]);
            unsigned a3 = f2tf32(As[wm + g + 8][k8 + q + 4]);
#pragma unroll
            for (int nt = 0; nt < 16; nt++) {
                int n = nt * 8 + g;
                unsigned bh0 = __float_as_uint(Bh[k8 + q][n]);
                unsigned bh1 = __float_as_uint(Bh[k8 + q + 4][n]);
                unsigned bl0 = __float_as_uint(Bl[k8 + q][n]);
                unsigned bl1 = __float_as_uint(Bl[k8 + q + 4][n]);
                mma_tf32(acc[nt], a0, a1, a2, a3, bh0, bh1);
                mma_tf32(acc[nt], a0, a1, a2, a3, bl0, bl1);
            }
        }
        __syncthreads();
    }

    // epilogue: D[g][2q],D[g][2q+1],D[g+8][2q],D[g+8][2q+1] per n-tile
    unsigned* gout = (unsigned*)d_g;   // [N][64] uints (2 bf16 each)
    int r0 = m0 + wm + g;
    int r1 = r0 + 8;
    float s0 = (r0 < N_NODES) ? d_dinv[r0] : 0.0f;
    float s1 = (r1 < N_NODES) ? d_dinv[r1] : 0.0f;
#pragma unroll
    for (int nt = 0; nt < 16; nt++) {
        int cu = nt * 4 + q;   // uint index within row (col/2)
        if (r0 < N_NODES) {
            __nv_bfloat162 p = __floats2bfloat162_rn(s0 * acc[nt][0], s0 * acc[nt][1]);
            gout[(size_t)r0 * 64 + cu] = *reinterpret_cast<unsigned*>(&p);
        }
        if (r1 < N_NODES) {
            __nv_bfloat162 p = __floats2bfloat162_rn(s1 * acc[nt][2], s1 * acc[nt][3]);
            gout[(size_t)r1 * 64 + cu] = *reinterpret_cast<unsigned*>(&p);
        }
    }
}

// ---------------- aggregation: h = relu(dinv_i * (g_i + Σ g_src) + b) --------
__device__ __forceinline__ float4 ld_g(int row, int lane) {
    uint2 u = __ldg(&d_g[(size_t)row * 32 + lane]);
    float2 f0 = __bfloat1622float2(*reinterpret_cast<__nv_bfloat162*>(&u.x));
    float2 f1 = __bfloat1622float2(*reinterpret_cast<__nv_bfloat162*>(&u.y));
    return make_float4(f0.x, f0.y, f1.x, f1.y);
}

__global__ __launch_bounds__(256) void k_agg(const float* __restrict__ bias) {
    int gw = (blockIdx.x * blockDim.x + threadIdx.x) >> 5;
    if (gw >= N_NODES) return;
    int lane = threadIdx.x & 31;

    int beg = d_off[gw];
    int end = d_off[gw + 1];

    float4 acc = ld_g(gw, lane);   // self term
    int j = beg;
    for (; j + 8 <= end; j += 8) {
        int s0 = d_csr[j + 0];
        int s1 = d_csr[j + 1];
        int s2 = d_csr[j + 2];
        int s3 = d_csr[j + 3];
        int s4 = d_csr[j + 4];
        int s5 = d_csr[j + 5];
        int s6 = d_csr[j + 6];
        int s7 = d_csr[j + 7];
        float4 a0 = ld_g(s0, lane);
        float4 a1 = ld_g(s1, lane);
        float4 a2 = ld_g(s2, lane);
        float4 a3 = ld_g(s3, lane);
        float4 a4 = ld_g(s4, lane);
        float4 a5 = ld_g(s5, lane);
        float4 a6 = ld_g(s6, lane);
        float4 a7 = ld_g(s7, lane);
        acc.x += ((a0.x + a1.x) + (a2.x + a3.x)) + ((a4.x + a5.x) + (a6.x + a7.x));
        acc.y += ((a0.y + a1.y) + (a2.y + a3.y)) + ((a4.y + a5.y) + (a6.y + a7.y));
        acc.z += ((a0.z + a1.z) + (a2.z + a3.z)) + ((a4.z + a5.z) + (a6.z + a7.z));
        acc.w += ((a0.w + a1.w) + (a2.w + a3.w)) + ((a4.w + a5.w) + (a6.w + a7.w));
    }
    for (; j < end; j++) {
        float4 a = ld_g(d_csr[j], lane);
        acc.x += a.x; acc.y += a.y; acc.z += a.z; acc.w += a.w;
    }

    float  s  = d_dinv[gw];
    float4 b4 = ((const float4*)bias)[lane];
    float4 r;
    r.x = fmaxf(fmaf(s, acc.x, b4.x), 0.0f);
    r.y = fmaxf(fmaf(s, acc.y, b4.y), 0.0f);
    r.z = fmaxf(fmaf(s, acc.z, b4.z), 0.0f);
    r.w = fmaxf(fmaf(s, acc.w, b4.w), 0.0f);
    d_h4[gw * 32 + lane] = r;
}

// ---------------- mean pool (batch is sorted → contiguous ranges) ------------
// launch with 512 threads (4 segments x 128 channels)
__global__ __launch_bounds__(512) void k_pool() {
    __shared__ float red[4][CH];
    int g   = blockIdx.x;
    int c   = threadIdx.x & 127;
    int seg = threadIdx.x >> 7;
    int b = d_gstart[g], e = d_gstart[g + 1];
    const float* h = (const float*)d_h4;
    float s = 0.0f;
    for (int i = b + seg; i < e; i += 4) s += h[(size_t)i * CH + c];
    red[seg][c] = s;
    __syncthreads();
    if (seg == 0) {
        float tot = (red[0][c] + red[1][c]) + (red[2][c] + red[3][c]);
        float cnt = (float)(e - b);
        d_pool[g * CH + c] = tot / fmaxf(cnt, 1.0f);
    }
}

// ---------------- head: out = pooled @ Wc + bc -------------------------------
__global__ void k_final(const float* __restrict__ Wc, const float* __restrict__ bc,
                        float* __restrict__ out) {
    int t = threadIdx.x;
    if (t >= NGRAPH * 2) return;
    int g = t >> 1, o = t & 1;
    float s = 0.0f;
#pragma unroll 16
    for (int k = 0; k < CH; k++) s += d_pool[g * CH + k] * Wc[k * 2 + o];
    out[t] = s + bc[o];
}

// ---------------- launch -----------------------------------------------------
extern "C" void kernel_launch(void* const* d_in, const int* in_sizes, int n_in,
                              void* d_out, int out_size) {
    const float* x     = (const float*)d_in[0];
    const int*   ei    = (const int*)d_in[1];     // [2, E]: src then dst
    const int*   batch = (const int*)d_in[2];
    const float* W1 = (const float*)d_in[3];
    const float* b1 = (const float*)d_in[4];
    const float* W2 = (const float*)d_in[5];
    const float* b2 = (const float*)d_in[6];
    const float* W3 = (const float*)d_in[7];
    const float* b3 = (const float*)d_in[8];
    const float* Wc = (const float*)d_in[9];
    const float* bc = (const float*)d_in[10];
    float* out = (float*)d_out;

    const int* src = ei;
    const int* dst = ei + N_EDGES;

    int gN = (N_NODES + 255) / 256;
    int gE = (N_EDGES + 255) / 256;
    int gGemm = (N_NODES + 127) / 128;
    int gAgg  = (N_NODES * 32 + 255) / 256;

    k_zero<<<gN, 256>>>();
    k_hist<<<gE, 256>>>(dst, batch);
    k_scanA<<<NBLK, SCAN_B>>>();
    k_scanB<<<1, 128>>>();
    k_scanC<<<gN, 256>>>();
    k_scatter<<<gE, 256>>>(src, dst);

    // layer 1 (input x)
    k_gemm_tc<<<gGemm, 256>>>(x, W1);
    k_agg<<<gAgg, 256>>>(b1);
    // layer 2
    k_gemm_tc<<<gGemm, 256>>>(nullptr, W2);
    k_agg<<<gAgg, 256>>>(b2);
    // layer 3
    k_gemm_tc<<<gGemm, 256>>>(nullptr, W3);
    k_agg<<<gAgg, 256>>>(b3);

    k_pool<<<NGRAPH, 512>>>();
    k_final<<<1, 128>>>(Wc, bc, out);
}

// round 7
// speedup vs baseline: 1.8517x; 1.3008x over previous
#include <cuda_runtime.h>
#include <cuda_bf16.h>

#define N_NODES 50000
#define N_EDGES 800000
#define CH      128
#define NGRAPH  64
#define SCAN_B  512
#define NBLK    ((N_NODES + SCAN_B - 1) / SCAN_B)   // 98

// ---------------- scratch (__device__ globals; no allocation) ----------------
__device__ int    d_deg[N_NODES];
__device__ int    d_off[N_NODES + 1];
__device__ int    d_cur[N_NODES];
__device__ int    d_csr[N_EDGES];
__device__ int    d_tmp[N_NODES];
__device__ int    d_bsum[NBLK];
__device__ int    d_bpref[NBLK];
__device__ float  d_dinv[N_NODES];
__device__ int    d_gcount[NGRAPH];
__device__ int    d_gstart[NGRAPH + 1];
__device__ uint2  d_g[N_NODES * (CH / 4)];    // g = dinv * (h @ W), bf16 (4 ch per uint2)
__device__ float4 d_h4[N_NODES * (CH / 4)];   // layer activations, fp32
__device__ float  d_pool[NGRAPH * CH];
// W pre-packed into m16n8k8 B-fragment layout, tf32: [layer][ks(16)][nt(16)][lane(32)]
__device__ uint2  d_wpk[3 * 16 * 16 * 32];

// ---------------- setup kernels ----------------
__global__ void k_zero() {
    int i = blockIdx.x * blockDim.x + threadIdx.x;
    if (i < N_NODES) d_deg[i] = 0;
    if (i < NGRAPH)  d_gcount[i] = 0;
}

__global__ void k_hist(const int* __restrict__ dst, const int* __restrict__ batch) {
    int i = blockIdx.x * blockDim.x + threadIdx.x;
    if (i < N_EDGES) atomicAdd(&d_deg[dst[i]], 1);
    if (i < N_NODES) atomicAdd(&d_gcount[batch[i]], 1);
}

__global__ void k_scanA() {
    __shared__ int s[SCAN_B];
    int t = threadIdx.x;
    int i = blockIdx.x * SCAN_B + t;
    int x = (i < N_NODES) ? d_deg[i] : 0;
    s[t] = x;
    __syncthreads();
    for (int o = 1; o < SCAN_B; o <<= 1) {
        int v = (t >= o) ? s[t - o] : 0;
        __syncthreads();
        s[t] += v;
        __syncthreads();
    }
    if (i < N_NODES) d_tmp[i] = s[t];
    if (t == SCAN_B - 1) d_bsum[blockIdx.x] = s[t];
}

__global__ void k_scanB() {
    __shared__ int s[128];
    int t = threadIdx.x;

    int v = (t < NBLK) ? d_bsum[t] : 0;
    s[t] = v;
    __syncthreads();
#pragma unroll
    for (int o = 1; o < 128; o <<= 1) {
        int u = (t >= o) ? s[t - o] : 0;
        __syncthreads();
        s[t] += u;
        __syncthreads();
    }
    if (t < NBLK) d_bpref[t] = s[t] - v;
    __syncthreads();

    int c = (t < NGRAPH) ? d_gcount[t] : 0;
    s[t] = c;
    __syncthreads();
#pragma unroll
    for (int o = 1; o < 128; o <<= 1) {
        int u = (t >= o) ? s[t - o] : 0;
        __syncthreads();
        s[t] += u;
        __syncthreads();
    }
    if (t < NGRAPH) d_gstart[t] = s[t] - c;
    if (t == NGRAPH - 1) d_gstart[NGRAPH] = s[t];
}

__global__ void k_scanC() {
    int i = blockIdx.x * blockDim.x + threadIdx.x;
    if (i >= N_NODES) return;
    int incl = d_tmp[i] + d_bpref[i / SCAN_B];
    int deg  = d_deg[i];
    d_off[i + 1] = incl;
    d_cur[i]     = incl - deg;
    d_dinv[i]    = rsqrtf((float)deg + 1.0f);
    if (i == 0) d_off[0] = 0;
}

__global__ void k_scatter(const int* __restrict__ src, const int* __restrict__ dst) {
    int e = blockIdx.x * blockDim.x + threadIdx.x;
    if (e >= N_EDGES) return;
    int p = atomicAdd(&d_cur[dst[e]], 1);
    d_csr[p] = src[e];
}

// ---------------- tf32 helpers ----------------
__device__ __forceinline__ unsigned f2tf32(float f) {
    unsigned u;
    asm("cvt.rna.tf32.f32 %0, %1;" : "=r"(u) : "f"(f));
    return u;
}

__device__ __forceinline__ void mma_tf32(float c[4], unsigned a0, unsigned a1,
                                         unsigned a2, unsigned a3,
                                         unsigned b0, unsigned b1) {
    asm volatile(
        "mma.sync.aligned.m16n8k8.row.col.f32.tf32.tf32.f32 "
        "{%0,%1,%2,%3}, {%4,%5,%6,%7}, {%8,%9}, {%0,%1,%2,%3};"
        : "+f"(c[0]), "+f"(c[1]), "+f"(c[2]), "+f"(c[3])
        : "r"(a0), "r"(a1), "r"(a2), "r"(a3), "r"(b0), "r"(b1));
}

// ---------------- pack W into B-fragment layout (tf32) -----------------------
// wpk[((m*16+ks)*16+nt)*32+lane] = { tf32 W[ks*8 + q][nt*8 + g],
//                                    tf32 W[ks*8 + q + 4][nt*8 + g] },  q=lane&3, g=lane>>2
__global__ void k_pack_w(const float* __restrict__ W1, const float* __restrict__ W2,
                         const float* __restrict__ W3) {
    int t = blockIdx.x * blockDim.x + threadIdx.x;
    if (t >= 3 * 16 * 16 * 32) return;
    int m    = t / (16 * 16 * 32);
    int rem  = t - m * (16 * 16 * 32);
    int ks   = rem >> 9;
    int nt   = (rem >> 5) & 15;
    int lane = rem & 31;
    int q = lane & 3, g = lane >> 2;
    const float* W = (m == 0) ? W1 : (m == 1) ? W2 : W3;
    int k = ks * 8 + q;
    int n = nt * 8 + g;
    uint2 u;
    u.x = f2tf32(W[k * CH + n]);
    u.y = f2tf32(W[(k + 4) * CH + n]);
    d_wpk[t] = u;
}

// ---------------- GEMM: g = bf16(dinv ⊙ (A @ W)) via tf32 mma ----------------
// A [N,128] fp32 -> tf32 at staging; W from d_wpk fragments (single tf32).
// block 256 thr = 8 warps; tile M=128 x N=128; warp: 16 rows x 128 cols.
// per k16-chunk: stage A (cvt) + copy 8KB of W-fragments; inner: LDS.64 B + 1 MMA.
#define APAD 20
__global__ __launch_bounds__(256) void k_gemm_tc(const float* __restrict__ A_,
                                                 int layer) {
    __shared__ unsigned As[128][APAD];     // [row][k] tf32 bits
    __shared__ uint2    Bp[2][16][32];     // [ks][nt][lane] fragment pairs

    const float* Aptr = A_ ? A_ : (const float*)d_h4;

    int tid  = threadIdx.x;
    int wid  = tid >> 5;
    int lane = tid & 31;
    int g    = lane >> 2;   // 0..7
    int q    = lane & 3;    // 0..3
    int m0   = blockIdx.x * 128;
    int wm   = wid * 16;    // warp row strip

    const uint2* wbase = d_wpk + layer * (16 * 16 * 32);

    float acc[16][4];
#pragma unroll
    for (int nt = 0; nt < 16; nt++)
#pragma unroll
        for (int j = 0; j < 4; j++) acc[nt][j] = 0.0f;

    for (int c = 0; c < 8; c++) {          // k16 chunks
        int kc = c * 16;
        // stage A: 128 rows x 16 k, cvt to tf32 (512 float4, 2 per thread)
#pragma unroll
        for (int i = 0; i < 2; i++) {
            int idx = tid + 256 * i;
            int row = idx >> 2;
            int q4  = (idx & 3) * 4;
            float4 av = make_float4(0.f, 0.f, 0.f, 0.f);
            if (m0 + row < N_NODES)
                av = *(const float4*)&Aptr[(size_t)(m0 + row) * CH + kc + q4];
            As[row][q4 + 0] = f2tf32(av.x);
            As[row][q4 + 1] = f2tf32(av.y);
            As[row][q4 + 2] = f2tf32(av.z);
            As[row][q4 + 3] = f2tf32(av.w);
        }
        // stage W fragments: 2 ks * 16 nt * 32 lanes uint2 = 512 uint4, 2/thread
        {
            const uint4* src4 = (const uint4*)(wbase + (size_t)(2 * c) * 16 * 32);
            uint4* dst4 = (uint4*)&Bp[0][0][0];
            dst4[tid]       = src4[tid];
            dst4[tid + 256] = src4[tid + 256];
        }
        __syncthreads();

#pragma unroll
        for (int ks = 0; ks < 2; ks++) {
            int k8 = ks * 8;
            unsigned a0 = As[wm + g][k8 + q];
            unsigned a1 = As[wm + g + 8][k8 + q];
            unsigned a2 = As[wm + g][k8 + q + 4];
            unsigned a3 = As[wm + g + 8][k8 + q + 4];
#pragma unroll
            for (int nt = 0; nt < 16; nt++) {
                uint2 b = Bp[ks][nt][lane];
                mma_tf32(acc[nt], a0, a1, a2, a3, b.x, b.y);
            }
        }
        __syncthreads();
    }

    // epilogue: rows wm+g / wm+g+8, cols nt*8 + 2q, 2q+1
    unsigned* gout = (unsigned*)d_g;   // [N][64] uints (2 bf16 each)
    int r0 = m0 + wm + g;
    int r1 = r0 + 8;
    float s0 = (r0 < N_NODES) ? d_dinv[r0] : 0.0f;
    float s1 = (r1 < N_NODES) ? d_dinv[r1] : 0.0f;
#pragma unroll
    for (int nt = 0; nt < 16; nt++) {
        int cu = nt * 4 + q;
        if (r0 < N_NODES) {
            __nv_bfloat162 p = __floats2bfloat162_rn(s0 * acc[nt][0], s0 * acc[nt][1]);
            gout[(size_t)r0 * 64 + cu] = *reinterpret_cast<unsigned*>(&p);
        }
        if (r1 < N_NODES) {
            __nv_bfloat162 p = __floats2bfloat162_rn(s1 * acc[nt][2], s1 * acc[nt][3]);
            gout[(size_t)r1 * 64 + cu] = *reinterpret_cast<unsigned*>(&p);
        }
    }
}

// ---------------- aggregation: h = relu(dinv_i * (g_i + Σ g_src) + b) --------
__device__ __forceinline__ float4 ld_g(int row, int lane) {
    uint2 u = __ldg(&d_g[(size_t)row * 32 + lane]);
    float2 f0 = __bfloat1622float2(*reinterpret_cast<__nv_bfloat162*>(&u.x));
    float2 f1 = __bfloat1622float2(*reinterpret_cast<__nv_bfloat162*>(&u.y));
    return make_float4(f0.x, f0.y, f1.x, f1.y);
}

__global__ __launch_bounds__(256) void k_agg(const float* __restrict__ bias) {
    int gw = (blockIdx.x * blockDim.x + threadIdx.x) >> 5;
    if (gw >= N_NODES) return;
    int lane = threadIdx.x & 31;

    int beg = d_off[gw];
    int end = d_off[gw + 1];

    float4 acc = ld_g(gw, lane);   // self term
    int j = beg;
    for (; j + 8 <= end; j += 8) {
        int s0 = d_csr[j + 0];
        int s1 = d_csr[j + 1];
        int s2 = d_csr[j + 2];
        int s3 = d_csr[j + 3];
        int s4 = d_csr[j + 4];
        int s5 = d_csr[j + 5];
        int s6 = d_csr[j + 6];
        int s7 = d_csr[j + 7];
        float4 a0 = ld_g(s0, lane);
        float4 a1 = ld_g(s1, lane);
        float4 a2 = ld_g(s2, lane);
        float4 a3 = ld_g(s3, lane);
        float4 a4 = ld_g(s4, lane);
        float4 a5 = ld_g(s5, lane);
        float4 a6 = ld_g(s6, lane);
        float4 a7 = ld_g(s7, lane);
        acc.x += ((a0.x + a1.x) + (a2.x + a3.x)) + ((a4.x + a5.x) + (a6.x + a7.x));
        acc.y += ((a0.y + a1.y) + (a2.y + a3.y)) + ((a4.y + a5.y) + (a6.y + a7.y));
        acc.z += ((a0.z + a1.z) + (a2.z + a3.z)) + ((a4.z + a5.z) + (a6.z + a7.z));
        acc.w += ((a0.w + a1.w) + (a2.w + a3.w)) + ((a4.w + a5.w) + (a6.w + a7.w));
    }
    for (; j < end; j++) {
        float4 a = ld_g(d_csr[j], lane);
        acc.x += a.x; acc.y += a.y; acc.z += a.z; acc.w += a.w;
    }

    float  s  = d_dinv[gw];
    float4 b4 = ((const float4*)bias)[lane];
    float4 r;
    r.x = fmaxf(fmaf(s, acc.x, b4.x), 0.0f);
    r.y = fmaxf(fmaf(s, acc.y, b4.y), 0.0f);
    r.z = fmaxf(fmaf(s, acc.z, b4.z), 0.0f);
    r.w = fmaxf(fmaf(s, acc.w, b4.w), 0.0f);
    d_h4[gw * 32 + lane] = r;
}

// ---------------- mean pool (batch is sorted → contiguous ranges) ------------
// launch with 512 threads (4 segments x 128 channels)
__global__ __launch_bounds__(512) void k_pool() {
    __shared__ float red[4][CH];
    int g   = blockIdx.x;
    int c   = threadIdx.x & 127;
    int seg = threadIdx.x >> 7;
    int b = d_gstart[g], e = d_gstart[g + 1];
    const float* h = (const float*)d_h4;
    float s = 0.0f;
    for (int i = b + seg; i < e; i += 4) s += h[(size_t)i * CH + c];
    red[seg][c] = s;
    __syncthreads();
    if (seg == 0) {
        float tot = (red[0][c] + red[1][c]) + (red[2][c] + red[3][c]);
        float cnt = (float)(e - b);
        d_pool[g * CH + c] = tot / fmaxf(cnt, 1.0f);
    }
}

// ---------------- head: out = pooled @ Wc + bc -------------------------------
__global__ void k_final(const float* __restrict__ Wc, const float* __restrict__ bc,
                        float* __restrict__ out) {
    int t = threadIdx.x;
    if (t >= NGRAPH * 2) return;
    int g = t >> 1, o = t & 1;
    float s = 0.0f;
#pragma unroll 16
    for (int k = 0; k < CH; k++) s += d_pool[g * CH + k] * Wc[k * 2 + o];
    out[t] = s + bc[o];
}

// ---------------- launch -----------------------------------------------------
extern "C" void kernel_launch(void* const* d_in, const int* in_sizes, int n_in,
                              void* d_out, int out_size) {
    const float* x     = (const float*)d_in[0];
    const int*   ei    = (const int*)d_in[1];     // [2, E]: src then dst
    const int*   batch = (const int*)d_in[2];
    const float* W1 = (const float*)d_in[3];
    const float* b1 = (const float*)d_in[4];
    const float* W2 = (const float*)d_in[5];
    const float* b2 = (const float*)d_in[6];
    const float* W3 = (const float*)d_in[7];
    const float* b3 = (const float*)d_in[8];
    const float* Wc = (const float*)d_in[9];
    const float* bc = (const float*)d_in[10];
    float* out = (float*)d_out;

    const int* src = ei;
    const int* dst = ei + N_EDGES;

    int gN = (N_NODES + 255) / 256;
    int gE = (N_EDGES + 255) / 256;
    int gGemm = (N_NODES + 127) / 128;
    int gAgg  = (N_NODES * 32 + 255) / 256;
    int gPack = (3 * 16 * 16 * 32 + 255) / 256;

    k_zero<<<gN, 256>>>();
    k_hist<<<gE, 256>>>(dst, batch);
    k_scanA<<<NBLK, SCAN_B>>>();
    k_scanB<<<1, 128>>>();
    k_scanC<<<gN, 256>>>();
    k_scatter<<<gE, 256>>>(src, dst);
    k_pack_w<<<gPack, 256>>>(W1, W2, W3);

    // layer 1 (input x)
    k_gemm_tc<<<gGemm, 256>>>(x, 0);
    k_agg<<<gAgg, 256>>>(b1);
    // layer 2
    k_gemm_tc<<<gGemm, 256>>>(nullptr, 1);
    k_agg<<<gAgg, 256>>>(b2);
    // layer 3
    k_gemm_tc<<<gGemm, 256>>>(nullptr, 2);
    k_agg<<<gAgg, 256>>>(b3);

    k_pool<<<NGRAPH, 512>>>();
    k_final<<<1, 128>>>(Wc, bc, out);
}

// round 9
// speedup vs baseline: 1.9945x; 1.0772x over previous
#include <cuda_runtime.h>
#include <cuda_bf16.h>

#define N_NODES 50000
#define N_EDGES 800000
#define CH      128
#define NGRAPH  64
#define SCAN_B  512
#define NBLK    ((N_NODES + SCAN_B - 1) / SCAN_B)   // 98
#define AS_COLS 132
#define GEMM_SMEM (128 * AS_COLS * 4 + 16 * 16 * 32 * 8)   // 67584 + 65536 = 133120

// ---------------- scratch (__device__ globals; no allocation) ----------------
__device__ int    d_deg[N_NODES];
__device__ int    d_off[N_NODES + 1];
__device__ int    d_cur[N_NODES];
__device__ int    d_csr[N_EDGES];
__device__ int    d_tmp[N_NODES];
__device__ int    d_bsum[NBLK];
__device__ int    d_bpref[NBLK];
__device__ float  d_dinv[N_NODES];
__device__ int    d_gcount[NGRAPH];
__device__ int    d_gstart[NGRAPH + 1];
__device__ uint2  d_g[N_NODES * (CH / 4)];    // g = dinv * (h @ W), bf16 (4 ch per uint2)
__device__ float4 d_h4[N_NODES * (CH / 4)];   // layer activations, fp32
__device__ float  d_pool[NGRAPH * CH];
// W pre-packed into m16n8k8 B-fragment layout, tf32: [layer][ks(16)][nt(16)][lane(32)]
__device__ uint2  d_wpk[3 * 16 * 16 * 32];

// ---------------- setup kernels ----------------
__global__ void k_zero() {
    int i = blockIdx.x * blockDim.x + threadIdx.x;
    if (i < N_NODES) d_deg[i] = 0;
    if (i < NGRAPH)  d_gcount[i] = 0;
}

__global__ void k_hist(const int* __restrict__ dst, const int* __restrict__ batch) {
    int i = blockIdx.x * blockDim.x + threadIdx.x;
    if (i < N_EDGES) atomicAdd(&d_deg[dst[i]], 1);
    if (i < N_NODES) atomicAdd(&d_gcount[batch[i]], 1);
}

__global__ void k_scanA() {
    __shared__ int s[SCAN_B];
    int t = threadIdx.x;
    int i = blockIdx.x * SCAN_B + t;
    int x = (i < N_NODES) ? d_deg[i] : 0;
    s[t] = x;
    __syncthreads();
    for (int o = 1; o < SCAN_B; o <<= 1) {
        int v = (t >= o) ? s[t - o] : 0;
        __syncthreads();
        s[t] += v;
        __syncthreads();
    }
    if (i < N_NODES) d_tmp[i] = s[t];
    if (t == SCAN_B - 1) d_bsum[blockIdx.x] = s[t];
}

__global__ void k_scanB() {
    __shared__ int s[128];
    int t = threadIdx.x;

    int v = (t < NBLK) ? d_bsum[t] : 0;
    s[t] = v;
    __syncthreads();
#pragma unroll
    for (int o = 1; o < 128; o <<= 1) {
        int u = (t >= o) ? s[t - o] : 0;
        __syncthreads();
        s[t] += u;
        __syncthreads();
    }
    if (t < NBLK) d_bpref[t] = s[t] - v;
    __syncthreads();

    int c = (t < NGRAPH) ? d_gcount[t] : 0;
    s[t] = c;
    __syncthreads();
#pragma unroll
    for (int o = 1; o < 128; o <<= 1) {
        int u = (t >= o) ? s[t - o] : 0;
        __syncthreads();
        s[t] += u;
        __syncthreads();
    }
    if (t < NGRAPH) d_gstart[t] = s[t] - c;
    if (t == NGRAPH - 1) d_gstart[NGRAPH] = s[t];
}

__global__ void k_scanC() {
    int i = blockIdx.x * blockDim.x + threadIdx.x;
    if (i >= N_NODES) return;
    int incl = d_tmp[i] + d_bpref[i / SCAN_B];
    int deg  = d_deg[i];
    d_off[i + 1] = incl;
    d_cur[i]     = incl - deg;
    d_dinv[i]    = rsqrtf((float)deg + 1.0f);
    if (i == 0) d_off[0] = 0;
}

__global__ void k_scatter(const int* __restrict__ src, const int* __restrict__ dst) {
    int e = blockIdx.x * blockDim.x + threadIdx.x;
    if (e >= N_EDGES) return;
    int p = atomicAdd(&d_cur[dst[e]], 1);
    d_csr[p] = src[e];
}

// ---------------- tf32 helpers ----------------
__device__ __forceinline__ unsigned f2tf32(float f) {
    unsigned u;
    asm("cvt.rna.tf32.f32 %0, %1;" : "=r"(u) : "f"(f));
    return u;
}

__device__ __forceinline__ void mma_tf32(float c[4], unsigned a0, unsigned a1,
                                         unsigned a2, unsigned a3,
                                         unsigned b0, unsigned b1) {
    asm volatile(
        "mma.sync.aligned.m16n8k8.row.col.f32.tf32.tf32.f32 "
        "{%0,%1,%2,%3}, {%4,%5,%6,%7}, {%8,%9}, {%0,%1,%2,%3};"
        : "+f"(c[0]), "+f"(c[1]), "+f"(c[2]), "+f"(c[3])
        : "r"(a0), "r"(a1), "r"(a2), "r"(a3), "r"(b0), "r"(b1));
}

// ---------------- pack W into B-fragment layout (tf32) -----------------------
__global__ void k_pack_w(const float* __restrict__ W1, const float* __restrict__ W2,
                         const float* __restrict__ W3) {
    int t = blockIdx.x * blockDim.x + threadIdx.x;
    if (t >= 3 * 16 * 16 * 32) return;
    int m    = t / (16 * 16 * 32);
    int rem  = t - m * (16 * 16 * 32);
    int ks   = rem >> 9;
    int nt   = (rem >> 5) & 15;
    int lane = rem & 31;
    int q = lane & 3, g = lane >> 2;
    const float* W = (m == 0) ? W1 : (m == 1) ? W2 : W3;
    int k = ks * 8 + q;
    int n = nt * 8 + g;
    uint2 u;
    u.x = f2tf32(W[k * CH + n]);
    u.y = f2tf32(W[(k + 4) * CH + n]);
    d_wpk[t] = u;
}

// ---------------- GEMM: g = bf16(dinv ⊙ (A @ W)) via tf32 mma ----------------
// Full-tile single-stage: A (128x128 tf32, 66KB) + all W fragments (64KB) in
// dynamic smem, ONE __syncthreads, then an uninterrupted 256-MMA stream/warp.
__global__ __launch_bounds__(256) void k_gemm_tc(const float* __restrict__ A_,
                                                 int layer) {
    extern __shared__ unsigned dynsmem[];
    unsigned* As = dynsmem;                                 // [128][AS_COLS]
    uint2*    Bp = (uint2*)(dynsmem + 128 * AS_COLS);       // [ks16][nt16][lane32]

    const float* Aptr = A_ ? A_ : (const float*)d_h4;

    int tid  = threadIdx.x;
    int wid  = tid >> 5;
    int lane = tid & 31;
    int g    = lane >> 2;   // 0..7
    int q    = lane & 3;    // 0..3
    int m0   = blockIdx.x * 128;
    int wm   = wid * 16;    // warp row strip

    // stage A: 128 rows x 128 cols fp32 -> tf32 (4096 float4, 16 per thread)
#pragma unroll
    for (int i = 0; i < 16; i++) {
        int idx = tid + 256 * i;
        int row = idx >> 5;
        int c4  = (idx & 31) * 4;
        float4 av = make_float4(0.f, 0.f, 0.f, 0.f);
        if (m0 + row < N_NODES)
            av = *(const float4*)&Aptr[(size_t)(m0 + row) * CH + c4];
        As[row * AS_COLS + c4 + 0] = f2tf32(av.x);
        As[row * AS_COLS + c4 + 1] = f2tf32(av.y);
        As[row * AS_COLS + c4 + 2] = f2tf32(av.z);
        As[row * AS_COLS + c4 + 3] = f2tf32(av.w);
    }
    // stage all W fragments: 16*16*32 uint2 = 4096 uint4, 16 per thread
    {
        const uint4* src4 = (const uint4*)(d_wpk + (size_t)layer * (16 * 16 * 32));
        uint4* dst4 = (uint4*)Bp;
#pragma unroll
        for (int i = 0; i < 16; i++) dst4[tid + 256 * i] = src4[tid + 256 * i];
    }
    __syncthreads();

    float acc[16][4];
#pragma unroll
    for (int nt = 0; nt < 16; nt++)
#pragma unroll
        for (int j = 0; j < 4; j++) acc[nt][j] = 0.0f;

#pragma unroll
    for (int ks = 0; ks < 16; ks++) {
        int k8 = ks * 8;
        unsigned a0 = As[(wm + g) * AS_COLS + k8 + q];
        unsigned a1 = As[(wm + g + 8) * AS_COLS + k8 + q];
        unsigned a2 = As[(wm + g) * AS_COLS + k8 + q + 4];
        unsigned a3 = As[(wm + g + 8) * AS_COLS + k8 + q + 4];
#pragma unroll
        for (int nt = 0; nt < 16; nt++) {
            uint2 b = Bp[(ks * 16 + nt) * 32 + lane];
            mma_tf32(acc[nt], a0, a1, a2, a3, b.x, b.y);
        }
    }

    // epilogue: rows wm+g / wm+g+8, cols nt*8 + 2q, 2q+1
    unsigned* gout = (unsigned*)d_g;   // [N][64] uints (2 bf16 each)
    int r0 = m0 + wm + g;
    int r1 = r0 + 8;
    float s0 = (r0 < N_NODES) ? d_dinv[r0] : 0.0f;
    float s1 = (r1 < N_NODES) ? d_dinv[r1] : 0.0f;
#pragma unroll
    for (int nt = 0; nt < 16; nt++) {
        int cu = nt * 4 + q;
        if (r0 < N_NODES) {
            __nv_bfloat162 p = __floats2bfloat162_rn(s0 * acc[nt][0], s0 * acc[nt][1]);
            gout[(size_t)r0 * 64 + cu] = *reinterpret_cast<unsigned*>(&p);
        }
        if (r1 < N_NODES) {
            __nv_bfloat162 p = __floats2bfloat162_rn(s1 * acc[nt][2], s1 * acc[nt][3]);
            gout[(size_t)r1 * 64 + cu] = *reinterpret_cast<unsigned*>(&p);
        }
    }
}

// ---------------- aggregation: h = relu(dinv_i * (g_i + Σ g_src) + b) --------
__device__ __forceinline__ float4 ld_g(int row, int lane) {
    uint2 u = __ldg(&d_g[(size_t)row * 32 + lane]);
    float2 f0 = __bfloat1622float2(*reinterpret_cast<__nv_bfloat162*>(&u.x));
    float2 f1 = __bfloat1622float2(*reinterpret_cast<__nv_bfloat162*>(&u.y));
    return make_float4(f0.x, f0.y, f1.x, f1.y);
}

__global__ __launch_bounds__(256) void k_agg(const float* __restrict__ bias) {
    int gw = (blockIdx.x * blockDim.x + threadIdx.x) >> 5;
    if (gw >= N_NODES) return;
    int lane = threadIdx.x & 31;

    int beg = d_off[gw];
    int end = d_off[gw + 1];

    float4 acc = ld_g(gw, lane);   // self term
    int j = beg;
    for (; j + 8 <= end; j += 8) {
        int s0 = d_csr[j + 0];
        int s1 = d_csr[j + 1];
        int s2 = d_csr[j + 2];
        int s3 = d_csr[j + 3];
        int s4 = d_csr[j + 4];
        int s5 = d_csr[j + 5];
        int s6 = d_csr[j + 6];
        int s7 = d_csr[j + 7];
        float4 a0 = ld_g(s0, lane);
        float4 a1 = ld_g(s1, lane);
        float4 a2 = ld_g(s2, lane);
        float4 a3 = ld_g(s3, lane);
        float4 a4 = ld_g(s4, lane);
        float4 a5 = ld_g(s5, lane);
        float4 a6 = ld_g(s6, lane);
        float4 a7 = ld_g(s7, lane);
        acc.x += ((a0.x + a1.x) + (a2.x + a3.x)) + ((a4.x + a5.x) + (a6.x + a7.x));
        acc.y += ((a0.y + a1.y) + (a2.y + a3.y)) + ((a4.y + a5.y) + (a6.y + a7.y));
        acc.z += ((a0.z + a1.z) + (a2.z + a3.z)) + ((a4.z + a5.z) + (a6.z + a7.z));
        acc.w += ((a0.w + a1.w) + (a2.w + a3.w)) + ((a4.w + a5.w) + (a6.w + a7.w));
    }
    for (; j < end; j++) {
        float4 a = ld_g(d_csr[j], lane);
        acc.x += a.x; acc.y += a.y; acc.z += a.z; acc.w += a.w;
    }

    float  s  = d_dinv[gw];
    float4 b4 = ((const float4*)bias)[lane];
    float4 r;
    r.x = fmaxf(fmaf(s, acc.x, b4.x), 0.0f);
    r.y = fmaxf(fmaf(s, acc.y, b4.y), 0.0f);
    r.z = fmaxf(fmaf(s, acc.z, b4.z), 0.0f);
    r.w = fmaxf(fmaf(s, acc.w, b4.w), 0.0f);
    d_h4[gw * 32 + lane] = r;
}

// ---------------- mean pool (batch is sorted → contiguous ranges) ------------
// launch with 512 threads (4 segments x 128 channels)
__global__ __launch_bounds__(512) void k_pool() {
    __shared__ float red[4][CH];
    int g   = blockIdx.x;
    int c   = threadIdx.x & 127;
    int seg = threadIdx.x >> 7;
    int b = d_gstart[g], e = d_gstart[g + 1];
    const float* h = (const float*)d_h4;
    float s = 0.0f;
    for (int i = b + seg; i < e; i += 4) s += h[(size_t)i * CH + c];
    red[seg][c] = s;
    __syncthreads();
    if (seg == 0) {
        float tot = (red[0][c] + red[1][c]) + (red[2][c] + red[3][c]);
        float cnt = (float)(e - b);
        d_pool[g * CH + c] = tot / fmaxf(cnt, 1.0f);
    }
}

// ---------------- head: out = pooled @ Wc + bc -------------------------------
__global__ void k_final(const float* __restrict__ Wc, const float* __restrict__ bc,
                        float* __restrict__ out) {
    int t = threadIdx.x;
    if (t >= NGRAPH * 2) return;
    int g = t >> 1, o = t & 1;
    float s = 0.0f;
#pragma unroll 16
    for (int k = 0; k < CH; k++) s += d_pool[g * CH + k] * Wc[k * 2 + o];
    out[t] = s + bc[o];
}

// ---------------- launch -----------------------------------------------------
extern "C" void kernel_launch(void* const* d_in, const int* in_sizes, int n_in,
                              void* d_out, int out_size) {
    const float* x     = (const float*)d_in[0];
    const int*   ei    = (const int*)d_in[1];     // [2, E]: src then dst
    const int*   batch = (const int*)d_in[2];
    const float* W1 = (const float*)d_in[3];
    const float* b1 = (const float*)d_in[4];
    const float* W2 = (const float*)d_in[5];
    const float* b2 = (const float*)d_in[6];
    const float* W3 = (const float*)d_in[7];
    const float* b3 = (const float*)d_in[8];
    const float* Wc = (const float*)d_in[9];
    const float* bc = (const float*)d_in[10];
    float* out = (float*)d_out;

    const int* src = ei;
    const int* dst = ei + N_EDGES;

    cudaFuncSetAttribute(k_gemm_tc, cudaFuncAttributeMaxDynamicSharedMemorySize, GEMM_SMEM);

    int gN = (N_NODES + 255) / 256;
    int gE = (N_EDGES + 255) / 256;
    int gGemm = (N_NODES + 127) / 128;
    int gAgg  = (N_NODES * 32 + 255) / 256;
    int gPack = (3 * 16 * 16 * 32 + 255) / 256;

    k_zero<<<gN, 256>>>();
    k_hist<<<gE, 256>>>(dst, batch);
    k_scanA<<<NBLK, SCAN_B>>>();
    k_scanB<<<1, 128>>>();
    k_scanC<<<gN, 256>>>();
    k_scatter<<<gE, 256>>>(src, dst);
    k_pack_w<<<gPack, 256>>>(W1, W2, W3);

    // layer 1 (input x)
    k_gemm_tc<<<gGemm, 256, GEMM_SMEM>>>(x, 0);
    k_agg<<<gAgg, 256>>>(b1);
    // layer 2
    k_gemm_tc<<<gGemm, 256, GEMM_SMEM>>>(nullptr, 1);
    k_agg<<<gAgg, 256>>>(b2);
    // layer 3
    k_gemm_tc<<<gGemm, 256, GEMM_SMEM>>>(nullptr, 2);
    k_agg<<<gAgg, 256>>>(b3);

    k_pool<<<NGRAPH, 512>>>();
    k_final<<<1, 128>>>(Wc, bc, out);
}